// round 6
// baseline (speedup 1.0000x reference)
#include <cuda_runtime.h>
#include <math.h>

#define NND 100000
#define NE  1600000
#define D   128
#define NCHUNK 4
#define CHSZ (NND / NCHUNK)          // 25000

typedef unsigned long long u64;

// Scratch (static device globals — no runtime allocation allowed)
__device__ float g_buf [NND * D];   // layer-1 messages
__device__ float g2_buf[NND * D];   // layer-2 messages (separate: pipeline WAR safety)
__device__ float acc_buf[NND * D];  // finalized activations h
__device__ float dis_buf[NND];
__device__ int   deg_buf[NND];
__device__ int   scan_tmp[NND];
__device__ int   row_ptr[NND + 1];
__device__ int   cursor[NND];
__device__ int   csr_src[NE];
__device__ int   bsum[256];
__device__ float Wf_buf[D * 64];    // fused head weight  Wp1@Wp2
__device__ float bF_buf[64];        // fused head bias    bp1@Wp2 + bp2

// ---------------- f32x2 helpers ----------------

__device__ __forceinline__ u64 ffma2(u64 a, u64 b, u64 c) {
    u64 d;
    asm("fma.rn.f32x2 %0, %1, %2, %3;" : "=l"(d) : "l"(a), "l"(b), "l"(c));
    return d;
}
__device__ __forceinline__ u64 pack_dup(float x) {
    u64 r;
    asm("mov.b64 %0, {%1, %1};" : "=l"(r) : "f"(x));
    return r;
}
__device__ __forceinline__ float2 unpack2(u64 v) {
    float2 r;
    asm("mov.b64 {%0, %1}, %2;" : "=f"(r.x), "=f"(r.y) : "l"(v));
    return r;
}

// ---------------- degree / normalization / CSR build ----------------

__global__ void k_init_deg() {
    int i = blockIdx.x * blockDim.x + threadIdx.x;
    if (i < NND) deg_buf[i] = 0;
}

__global__ void k_count_deg(const int* __restrict__ dst) {
    int e = blockIdx.x * blockDim.x + threadIdx.x;
    if (e < NE) atomicAdd(&deg_buf[dst[e]], 1);
}

__global__ void k_dis() {
    int i = blockIdx.x * blockDim.x + threadIdx.x;
    if (i < NND) dis_buf[i] = rsqrtf((float)(deg_buf[i] + 1));
}

#define SCB 512
#define SCAN_BLOCKS ((NND + SCB - 1) / SCB)   // 196

__global__ __launch_bounds__(SCB) void k_scan1() {
    __shared__ int sm[SCB];
    int i = blockIdx.x * SCB + threadIdx.x;
    int v = (i < NND) ? deg_buf[i] : 0;
    sm[threadIdx.x] = v;
    __syncthreads();
#pragma unroll
    for (int off = 1; off < SCB; off <<= 1) {
        int t = (threadIdx.x >= off) ? sm[threadIdx.x - off] : 0;
        __syncthreads();
        sm[threadIdx.x] += t;
        __syncthreads();
    }
    if (i < NND) scan_tmp[i] = sm[threadIdx.x];
    if (threadIdx.x == SCB - 1) bsum[blockIdx.x] = sm[SCB - 1];
}

__global__ __launch_bounds__(256) void k_scan2() {
    __shared__ int sm[256];
    int v = (threadIdx.x < SCAN_BLOCKS) ? bsum[threadIdx.x] : 0;
    sm[threadIdx.x] = v;
    __syncthreads();
#pragma unroll
    for (int off = 1; off < 256; off <<= 1) {
        int t = (threadIdx.x >= off) ? sm[threadIdx.x - off] : 0;
        __syncthreads();
        sm[threadIdx.x] += t;
        __syncthreads();
    }
    bsum[threadIdx.x] = sm[threadIdx.x];  // inclusive
}

__global__ __launch_bounds__(SCB) void k_scan3() {
    int i = blockIdx.x * SCB + threadIdx.x;
    if (i >= NND) return;
    int off = (blockIdx.x > 0) ? bsum[blockIdx.x - 1] : 0;
    int inc = scan_tmp[i] + off;
    int st  = inc - deg_buf[i];
    row_ptr[i] = st;
    cursor[i]  = st;
    if (i == NND - 1) row_ptr[NND] = inc;
}

__global__ void k_fill(const int* __restrict__ src, const int* __restrict__ dst) {
    int e = blockIdx.x * blockDim.x + threadIdx.x;
    if (e >= NE) return;
    int p = atomicAdd(&cursor[dst[e]], 1);
    csr_src[p] = src[e];
}

// ---------------- fused head weight precompute ----------------

__global__ __launch_bounds__(256) void k_fusew(const float* __restrict__ Wp1,
                                               const float* __restrict__ bp1,
                                               const float* __restrict__ Wp2,
                                               const float* __restrict__ bp2)
{
    int i = blockIdx.x * blockDim.x + threadIdx.x;
    if (i >= D * 64) return;
    int k = i >> 6, n = i & 63;
    float s = 0.0f;
#pragma unroll 8
    for (int j = 0; j < D; j++)
        s = fmaf(Wp1[k * D + j], Wp2[j * 64 + n], s);
    Wf_buf[i] = s;
    if (k == 0) {
        float t = bp2[n];
#pragma unroll 8
        for (int j = 0; j < D; j++)
            t = fmaf(bp1[j], Wp2[j * 64 + n], t);
        bF_buf[n] = t;
    }
}

// ---------------- GEMM: C[rows,BN] = A[rows,128] @ W[128,BN] + epilogue ----------------
// EPI 0: C = acc * dis[row]   (message-side scaling)
// EPI 2: C = log_softmax(acc + biasC) over row (BN=64)
// EPI 3: C = acc

template <int BN, int TN, int EPI>
__global__ __launch_bounds__(256, 2)
void gemm_k128(const float* __restrict__ A,
               const float* __restrict__ W,
               const float* __restrict__ biasC,
               const float* __restrict__ dis,
               float* __restrict__ C,
               int row_base, int Mend)
{
    constexpr int BM = 128, K = 128, KC = 32, TM = 8;
    constexpr int TP  = TN / 2;
    constexpr int SAP = KC + 4;
    __shared__ float As[BM * SAP];
    __shared__ u64   Ws2[KC * BN / 2];

    const int tid  = threadIdx.x;
    const int row0 = row_base + blockIdx.x * BM;
    const int tx   = tid & 15;
    const int ty   = tid >> 4;

    u64 acc[TM][TP];
#pragma unroll
    for (int i = 0; i < TM; i++)
#pragma unroll
        for (int j = 0; j < TP; j++) acc[i][j] = 0ULL;

    for (int kc = 0; kc < K; kc += KC) {
#pragma unroll
        for (int p = 0; p < (BM * KC / 4) / 256; p++) {
            int i  = tid + p * 256;
            int r  = i / (KC / 4);
            int c4 = i % (KC / 4);
            float4 v = make_float4(0.f, 0.f, 0.f, 0.f);
            int row = row0 + r;
            if (row < Mend)
                v = *(const float4*)(A + row * K + kc + c4 * 4);
            *(float4*)(As + r * SAP + c4 * 4) = v;
        }
#pragma unroll
        for (int p = 0; p < (KC * BN / 4) / 256; p++) {
            int i = tid + p * 256;
            ((float4*)Ws2)[i] = *(const float4*)(W + kc * BN + i * 4);
        }
        __syncthreads();

#pragma unroll 8
        for (int k = 0; k < KC; k++) {
            u64 wp[TP];
#pragma unroll
            for (int j = 0; j < TP; j++)
                wp[j] = Ws2[k * (BN / 2) + j * 16 + tx];
            float a[TM];
#pragma unroll
            for (int i = 0; i < TM; i++)
                a[i] = As[(ty * TM + i) * SAP + k];
            u64 ap[TM];
#pragma unroll
            for (int i = 0; i < TM; i++) ap[i] = pack_dup(a[i]);
#pragma unroll
            for (int i = 0; i < TM; i++)
#pragma unroll
                for (int j = 0; j < TP; j++)
                    acc[i][j] = ffma2(ap[i], wp[j], acc[i][j]);
        }
        __syncthreads();
    }

    if (EPI == 0 || EPI == 3) {
#pragma unroll
        for (int i = 0; i < TM; i++) {
            int row = row0 + ty * TM + i;
            if (row >= Mend) break;
            float s = (EPI == 0) ? dis[row] : 1.0f;
#pragma unroll
            for (int j = 0; j < TP; j++) {
                float2 v = unpack2(acc[i][j]);
                if (EPI == 0) { v.x *= s; v.y *= s; }
                *(float2*)(C + row * BN + 2 * (tx + j * 16)) = v;
            }
        }
    } else {  // EPI 2: BN=64, TP=2
        float2 b0 = *(const float2*)(biasC + 2 * tx);
        float2 b1 = *(const float2*)(biasC + 2 * (tx + 16));
#pragma unroll
        for (int i = 0; i < TM; i++) {
            int row = row0 + ty * TM + i;
            float2 v0 = unpack2(acc[i][0]);
            float2 v1 = unpack2(acc[i][1]);
            float t0 = v0.x + b0.x, t1 = v0.y + b0.y;
            float t2 = v1.x + b1.x, t3 = v1.y + b1.y;
            float m = fmaxf(fmaxf(t0, t1), fmaxf(t2, t3));
#pragma unroll
            for (int o = 8; o; o >>= 1) m = fmaxf(m, __shfl_xor_sync(0xFFFFFFFFu, m, o));
            float s = expf(t0 - m) + expf(t1 - m) + expf(t2 - m) + expf(t3 - m);
#pragma unroll
            for (int o = 8; o; o >>= 1) s += __shfl_xor_sync(0xFFFFFFFFu, s, o);
            float l = m + logf(s);
            if (row < Mend) {
                float2 r0, r1;
                r0.x = t0 - l; r0.y = t1 - l;
                r1.x = t2 - l; r1.y = t3 - l;
                *(float2*)(C + row * BN + 2 * tx)        = r0;
                *(float2*)(C + row * BN + 2 * (tx + 16)) = r1;
            }
        }
    }
}

// ---------------- CSR gather + finalize:  h[v] = relu(dis[v]*a + bias) ----------------
// SCALE_MSG=1: a = dis[v]*g[v] + sum dis[s]*g[s]   (layer 1: g unscaled)
// SCALE_MSG=0: a = g[v] + sum g[s]                 (layer 2: g pre-scaled by dis_s)

template <bool SCALE_MSG>
__global__ __launch_bounds__(256)
void k_gather_fin(const float* __restrict__ g, const float* __restrict__ dis,
                  const float* __restrict__ bias, float* __restrict__ h, int node0)
{
    int node = node0 + ((blockIdx.x * blockDim.x + threadIdx.x) >> 5);
    int lane = threadIdx.x & 31;
    if (node >= NND) return;
    int beg = row_ptr[node];
    int end = row_ptr[node + 1];
    const float4* gp = (const float4*)g;
    float4 a = gp[node * 32 + lane];          // self-loop message
    float dv = dis[node];
    if (SCALE_MSG) { a.x *= dv; a.y *= dv; a.z *= dv; a.w *= dv; }
    int e = beg;
    for (; e + 4 <= end; e += 4) {
        int s0 = __ldg(&csr_src[e + 0]);
        int s1 = __ldg(&csr_src[e + 1]);
        int s2 = __ldg(&csr_src[e + 2]);
        int s3 = __ldg(&csr_src[e + 3]);
        float4 v0 = gp[s0 * 32 + lane];
        float4 v1 = gp[s1 * 32 + lane];
        float4 v2 = gp[s2 * 32 + lane];
        float4 v3 = gp[s3 * 32 + lane];
        if (SCALE_MSG) {
            float d0 = __ldg(&dis[s0]), d1 = __ldg(&dis[s1]);
            float d2 = __ldg(&dis[s2]), d3 = __ldg(&dis[s3]);
            a.x = fmaf(v0.x, d0, a.x); a.y = fmaf(v0.y, d0, a.y);
            a.z = fmaf(v0.z, d0, a.z); a.w = fmaf(v0.w, d0, a.w);
            a.x = fmaf(v1.x, d1, a.x); a.y = fmaf(v1.y, d1, a.y);
            a.z = fmaf(v1.z, d1, a.z); a.w = fmaf(v1.w, d1, a.w);
            a.x = fmaf(v2.x, d2, a.x); a.y = fmaf(v2.y, d2, a.y);
            a.z = fmaf(v2.z, d2, a.z); a.w = fmaf(v2.w, d2, a.w);
            a.x = fmaf(v3.x, d3, a.x); a.y = fmaf(v3.y, d3, a.y);
            a.z = fmaf(v3.z, d3, a.z); a.w = fmaf(v3.w, d3, a.w);
        } else {
            a.x += v0.x + v1.x + v2.x + v3.x;
            a.y += v0.y + v1.y + v2.y + v3.y;
            a.z += v0.z + v1.z + v2.z + v3.z;
            a.w += v0.w + v1.w + v2.w + v3.w;
        }
    }
    for (; e < end; e++) {
        int s = __ldg(&csr_src[e]);
        float4 v = gp[s * 32 + lane];
        if (SCALE_MSG) {
            float ds = __ldg(&dis[s]);
            a.x = fmaf(v.x, ds, a.x); a.y = fmaf(v.y, ds, a.y);
            a.z = fmaf(v.z, ds, a.z); a.w = fmaf(v.w, ds, a.w);
        } else {
            a.x += v.x; a.y += v.y; a.z += v.z; a.w += v.w;
        }
    }
    // finalize: relu(dis[v]*a + bias)
    float4 b = ((const float4*)bias)[lane];
    float4 r;
    r.x = fmaxf(fmaf(a.x, dv, b.x), 0.f);
    r.y = fmaxf(fmaf(a.y, dv, b.y), 0.f);
    r.z = fmaxf(fmaf(a.z, dv, b.z), 0.f);
    r.w = fmaxf(fmaf(a.w, dv, b.w), 0.f);
    ((float4*)h)[node * 32 + lane] = r;
}

// ---------------- launch ----------------

extern "C" void kernel_launch(void* const* d_in, const int* in_sizes, int n_in,
                              void* d_out, int out_size)
{
    const float* x   = (const float*)d_in[0];
    const int*   ei  = (const int*)d_in[1];
    const int*   src = ei;
    const int*   dst = ei + NE;
    const float* W1  = (const float*)d_in[2];
    const float* b1  = (const float*)d_in[3];
    const float* W2  = (const float*)d_in[4];
    const float* b2  = (const float*)d_in[5];
    const float* Wp1 = (const float*)d_in[6];
    const float* bp1 = (const float*)d_in[7];
    const float* Wp2 = (const float*)d_in[8];
    const float* bp2 = (const float*)d_in[9];
    float* out = (float*)d_out;

    float *g_p, *g2_p, *acc_p, *dis_p, *wf_p, *bf_p;
    cudaGetSymbolAddress((void**)&g_p,   g_buf);
    cudaGetSymbolAddress((void**)&g2_p,  g2_buf);
    cudaGetSymbolAddress((void**)&acc_p, acc_buf);
    cudaGetSymbolAddress((void**)&dis_p, dis_buf);
    cudaGetSymbolAddress((void**)&wf_p,  Wf_buf);
    cudaGetSymbolAddress((void**)&bf_p,  bF_buf);

    // streams/events created once, outside any graph capture
    static cudaStream_t s2 = nullptr;
    static cudaEvent_t ev_fork, ev_csr, evA[NCHUNK], evB[NCHUNK], evC[NCHUNK], ev_end;
    if (!s2) {
        cudaStreamCreateWithFlags(&s2, cudaStreamNonBlocking);
        cudaEventCreateWithFlags(&ev_fork, cudaEventDisableTiming);
        cudaEventCreateWithFlags(&ev_csr,  cudaEventDisableTiming);
        cudaEventCreateWithFlags(&ev_end,  cudaEventDisableTiming);
        for (int c = 0; c < NCHUNK; c++) {
            cudaEventCreateWithFlags(&evA[c], cudaEventDisableTiming);
            cudaEventCreateWithFlags(&evB[c], cudaEventDisableTiming);
            cudaEventCreateWithFlags(&evC[c], cudaEventDisableTiming);
        }
    }

    const int GEMM_FULL_BLOCKS = (NND + 127) / 128;        // 782
    const int GEMM_CH_BLOCKS   = (CHSZ + 127) / 128;       // 196
    const int GATHER_CH_BLOCKS = (CHSZ * 32) / 256;        // 3125

    // ---- fork: CSR build + norm + head-weight fusion on s2, GEMM1 on main ----
    cudaEventRecord(ev_fork, 0);
    cudaStreamWaitEvent(s2, ev_fork, 0);

    k_fusew<<<(D * 64 + 255) / 256, 256, 0, s2>>>(Wp1, bp1, Wp2, bp2);
    k_init_deg<<<(NND + 255) / 256, 256, 0, s2>>>();
    k_count_deg<<<(NE + 255) / 256, 256, 0, s2>>>(dst);
    k_dis<<<(NND + 255) / 256, 256, 0, s2>>>();
    k_scan1<<<SCAN_BLOCKS, SCB, 0, s2>>>();
    k_scan2<<<1, 256, 0, s2>>>();
    k_scan3<<<SCAN_BLOCKS, SCB, 0, s2>>>();
    k_fill<<<(NE + 255) / 256, 256, 0, s2>>>(src, dst);
    cudaEventRecord(ev_csr, s2);

    // GEMM1 (main): g = x@W1 (plain, no dis dependency)
    gemm_k128<128, 8, 3><<<GEMM_FULL_BLOCKS, 256>>>(
        x, W1, nullptr, nullptr, g_p, 0, NND);

    cudaStreamWaitEvent(0, ev_csr, 0);

    // ---- pipeline: gather1 chunks (main) || gemm2 chunks (s2) ----
    for (int c = 0; c < NCHUNK; c++) {
        k_gather_fin<true><<<GATHER_CH_BLOCKS, 256>>>(g_p, dis_p, b1, acc_p, c * CHSZ);
        cudaEventRecord(evA[c], 0);
    }
    for (int c = 0; c < NCHUNK; c++) {
        cudaStreamWaitEvent(s2, evA[c], 0);
        gemm_k128<128, 8, 0><<<GEMM_CH_BLOCKS, 256, 0, s2>>>(
            acc_p, W2, nullptr, dis_p, g2_p, c * CHSZ, (c + 1) * CHSZ);
        cudaEventRecord(evB[c], s2);
    }

    // ---- pipeline: gather2 chunks (main, after all g2 ready) || head chunks (s2) ----
    cudaStreamWaitEvent(0, evB[NCHUNK - 1], 0);
    for (int c = 0; c < NCHUNK; c++) {
        k_gather_fin<false><<<GATHER_CH_BLOCKS, 256>>>(g2_p, dis_p, b2, acc_p, c * CHSZ);
        cudaEventRecord(evC[c], 0);
    }
    for (int c = 0; c < NCHUNK; c++) {
        cudaStreamWaitEvent(s2, evC[c], 0);
        gemm_k128<64, 4, 2><<<GEMM_CH_BLOCKS, 256, 0, s2>>>(
            acc_p, wf_p, bf_p, dis_p, out, c * CHSZ, (c + 1) * CHSZ);
    }
    cudaEventRecord(ev_end, s2);
    cudaStreamWaitEvent(0, ev_end, 0);
}